// round 5
// baseline (speedup 1.0000x reference)
#include <cuda_runtime.h>
#include <cuda_bf16.h>
#include <cstdint>

// Problem constants
#define LQ 1024
#define SQ 1024
#define NBATCH 8
#define EDIM 512
#define BHEADS 64   // NBATCH * HHEADS
#define LGRP 128    // l rows per group
#define NGRP 8

// ---------------- scratch (device globals; no allocations allowed) ----------
__device__ float g_qp[LQ * NBATCH * EDIM];          // (l, b, d)
__device__ float g_kp[SQ * NBATCH * EDIM];
__device__ float g_vp[SQ * NBATCH * EDIM];
__device__ float g_E[BHEADS * LGRP * SQ];           // (b, l_local, s) 33.5MB, L2-resident
__device__ float g_Z[BHEADS * LQ];                  // (b, l) row sums
__device__ float g_O[LQ * NBATCH * EDIM];           // (l, b, d) numerator out

// =================== helpers ================================================
__device__ __forceinline__ uint32_t smem_u32(const void* p) {
    uint32_t a;
    asm("{ .reg .u64 t; cvta.to.shared.u64 t, %1; cvt.u32.u64 %0, t; }" : "=r"(a) : "l"(p));
    return a;
}

__device__ __forceinline__ void ldsm_x4(uint32_t* r, uint32_t addr) {
    asm volatile("ldmatrix.sync.aligned.m8n8.x4.shared.b16 {%0,%1,%2,%3}, [%4];"
        : "=r"(r[0]), "=r"(r[1]), "=r"(r[2]), "=r"(r[3]) : "r"(addr));
}

__device__ __forceinline__ void mma_bf16(float* c, const uint32_t* a, const uint32_t* b) {
    asm volatile(
        "mma.sync.aligned.m16n8k16.row.col.f32.bf16.bf16.f32 "
        "{%0,%1,%2,%3}, {%4,%5,%6,%7}, {%8,%9}, {%0,%1,%2,%3};"
        : "+f"(c[0]), "+f"(c[1]), "+f"(c[2]), "+f"(c[3])
        : "r"(a[0]), "r"(a[1]), "r"(a[2]), "r"(a[3]), "r"(b[0]), "r"(b[1]));
}

__device__ __forceinline__ uint32_t pack2(__nv_bfloat16 a, __nv_bfloat16 b) {
    return (uint32_t)__bfloat16_as_ushort(a) | ((uint32_t)__bfloat16_as_ushort(b) << 16);
}
__device__ __forceinline__ void split2(float x, float y, uint32_t& hi, uint32_t& lo) {
    __nv_bfloat16 h0 = __float2bfloat16(x);
    __nv_bfloat16 h1 = __float2bfloat16(y);
    __nv_bfloat16 l0 = __float2bfloat16(x - __bfloat162float(h0));
    __nv_bfloat16 l1 = __float2bfloat16(y - __bfloat162float(h1));
    hi = pack2(h0, h1);
    lo = pack2(l0, l1);
}

// =================== HMMA strided batched GEMM (pipelined) ==================
// C[z][m][n] = epilogue( sum_k A(m,k)*B(n,k) )
// A(m,k) = A[z*aBS + m*aRS + k]                 (k contiguous)
// B(n,k) = BKFAST ? B[z*bBS + n*bS + k]         (k contiguous)
//                 : B[z*bBS + k*bS + n]         (n contiguous)
// C at    C[z*cBS + m*cRS + n]                  (n contiguous)
// EPI: 0 = alpha*(acc+bias) + beta*Cold
//      1 = EXPZ: e = exp(acc + Cold); store e; atomicAdd rowsum -> Zp[m*1024+z]
//      2 = DIVZ: (acc + Cold) / Zp[m*1024+z]
template<int BM, int BN, bool BKFAST, int EPI>
__global__ __launch_bounds__(256)
void mma_gemm(const float* __restrict__ A, long long aBS, long long aRS,
              const float* __restrict__ B, long long bBS, long long bS,
              float* __restrict__ C, long long cBS, long long cRS,
              const float* __restrict__ bias, float alpha, float beta,
              int K, float* __restrict__ Zp)
{
    constexpr int MT   = BM / 64;
    constexpr int NTL  = BN / 16;
    constexpr int ROWB = 144;
    constexpr int STG  = (BM + BN) * ROWB;
    constexpr int AREG = BM * 16 / 256;                    // float2 per thread
    constexpr int BREG2 = BKFAST ? BN * 16 / 256 : 1;      // float2 per thread
    constexpr int BREG1 = BKFAST ? 1 : BN * 32 / 256;      // float  per thread

    extern __shared__ __align__(16) char smem[];

    const int tid  = threadIdx.x;
    const int wid  = tid >> 5;
    const int lane = tid & 31;
    const int wm   = wid >> 1;
    const int wn   = wid & 1;
    const int mat  = lane >> 3;
    const int rw   = lane & 7;

    const int tile_n = blockIdx.x * BN;
    const int tile_m = blockIdx.y * BM;
    const int z      = blockIdx.z;

    const float* Az = A + (long long)z * aBS + (long long)tile_m * aRS;
    const float* Bz = B + (long long)z * bBS;

    float acc[MT][NTL][4];
#pragma unroll
    for (int i = 0; i < MT; i++)
#pragma unroll
        for (int j = 0; j < NTL; j++)
#pragma unroll
            for (int q = 0; q < 4; q++) acc[i][j][q] = 0.0f;

    const uint32_t s_u = smem_u32(smem);
    const uint32_t aAddr0 = s_u + (uint32_t)(wm * (BM / 4) + rw + (mat & 1) * 8) * ROWB
                                + (uint32_t)((mat >> 1) * 16);
    const uint32_t bAddr0 = s_u + (uint32_t)(BM * ROWB)
                                + (uint32_t)(wn * (BN / 2) + rw + (mat >> 1) * 8) * ROWB
                                + (uint32_t)((mat & 1) * 16);

    float2 aReg[AREG];
    float2 bReg2[BREG2];
    float  bReg1[BREG1];

    auto ldgA = [&](int ch) {
        const float* p = Az + (ch << 5);
#pragma unroll
        for (int j = 0; j < AREG; j++) {
            int i = tid + j * 256;
            int k2 = i & 15, r = i >> 4;
            aReg[j] = *reinterpret_cast<const float2*>(p + (long long)r * aRS + k2 * 2);
        }
    };
    auto stsA = [&](int st) {
        char* base = smem + st * STG;
#pragma unroll
        for (int j = 0; j < AREG; j++) {
            int i = tid + j * 256;
            int k2 = i & 15, r = i >> 4;
            uint32_t hi, lo;
            split2(aReg[j].x, aReg[j].y, hi, lo);
            char* rp = base + r * ROWB + k2 * 4;
            *reinterpret_cast<uint32_t*>(rp)      = hi;
            *reinterpret_cast<uint32_t*>(rp + 64) = lo;
        }
    };
    auto ldgB = [&](int ch) {
        if (BKFAST) {
            const float* p = Bz + (long long)tile_n * bS + (ch << 5);
#pragma unroll
            for (int j = 0; j < BREG2; j++) {
                int i = tid + j * 256;
                int k2 = i & 15, r = i >> 4;
                bReg2[j] = *reinterpret_cast<const float2*>(p + (long long)r * bS + k2 * 2);
            }
        } else {
            const float* p = Bz + tile_n + (long long)(ch << 5) * bS;
#pragma unroll
            for (int j = 0; j < BREG1; j++) {
                int i = tid + j * 256;
                int n = i & (BN - 1), k = i / BN;
                bReg1[j] = p[(long long)k * bS + n];
            }
        }
    };
    auto stsB = [&](int st) {
        char* base = smem + st * STG + BM * ROWB;
        if (BKFAST) {
#pragma unroll
            for (int j = 0; j < BREG2; j++) {
                int i = tid + j * 256;
                int k2 = i & 15, r = i >> 4;
                uint32_t hi, lo;
                split2(bReg2[j].x, bReg2[j].y, hi, lo);
                char* rp = base + r * ROWB + k2 * 4;
                *reinterpret_cast<uint32_t*>(rp)      = hi;
                *reinterpret_cast<uint32_t*>(rp + 64) = lo;
            }
        } else {
#pragma unroll
            for (int j = 0; j < BREG1; j++) {
                int i = tid + j * 256;
                int n = i & (BN - 1), k = i / BN;
                float v = bReg1[j];
                __nv_bfloat16 h = __float2bfloat16(v);
                __nv_bfloat16 l = __float2bfloat16(v - __bfloat162float(h));
                char* rp = base + n * ROWB + k * 2;
                *reinterpret_cast<unsigned short*>(rp)      = __bfloat16_as_ushort(h);
                *reinterpret_cast<unsigned short*>(rp + 64) = __bfloat16_as_ushort(l);
            }
        }
    };
    auto compute = [&](int st) {
        const uint32_t off = (uint32_t)(st * STG);
#pragma unroll
        for (int ks = 0; ks < 2; ks++) {
            uint32_t aH[MT][4], aL[MT][4];
#pragma unroll
            for (int mt = 0; mt < MT; mt++) {
                uint32_t ad = aAddr0 + off + (uint32_t)(mt * 16 * ROWB) + (uint32_t)(ks * 32);
                ldsm_x4(aH[mt], ad);
                ldsm_x4(aL[mt], ad + 64);
            }
            uint32_t bH[NTL][2], bL[NTL][2];
#pragma unroll
            for (int p = 0; p < NTL / 2; p++) {
                uint32_t bd = bAddr0 + off + (uint32_t)(p * 16 * ROWB) + (uint32_t)(ks * 32);
                uint32_t t[4];
                ldsm_x4(t, bd);
                bH[2 * p][0] = t[0]; bH[2 * p][1] = t[1];
                bH[2 * p + 1][0] = t[2]; bH[2 * p + 1][1] = t[3];
                ldsm_x4(t, bd + 64);
                bL[2 * p][0] = t[0]; bL[2 * p][1] = t[1];
                bL[2 * p + 1][0] = t[2]; bL[2 * p + 1][1] = t[3];
            }
#pragma unroll
            for (int mt = 0; mt < MT; mt++)
#pragma unroll
                for (int nt = 0; nt < NTL; nt++) {
                    mma_bf16(acc[mt][nt], aH[mt], bH[nt]);
                    mma_bf16(acc[mt][nt], aH[mt], bL[nt]);
                    mma_bf16(acc[mt][nt], aL[mt], bH[nt]);
                }
        }
    };

    const int nch = K >> 5;
    ldgA(0); ldgB(0);
    stsA(0); stsB(0);
    __syncthreads();
    for (int ch = 0; ch < nch; ch++) {
        const bool more = (ch + 1 < nch);
        if (more) { ldgA(ch + 1); ldgB(ch + 1); }
        compute(ch & 1);
        if (more) {
            stsA((ch + 1) & 1); stsB((ch + 1) & 1);
            __syncthreads();
        }
    }

    // ---- epilogue ----
    float* Cz = C + (long long)z * cBS;
#pragma unroll
    for (int mt = 0; mt < MT; mt++) {
        int m0 = tile_m + wm * (BM / 4) + mt * 16 + (lane >> 2);
#pragma unroll
        for (int half = 0; half < 2; half++) {
            int m = m0 + half * 8;
            float* crow = Cz + (long long)m * cRS;
            if (EPI == 1) {
                float rowsum = 0.0f;
#pragma unroll
                for (int nt = 0; nt < NTL; nt++) {
                    int n = tile_n + wn * (BN / 2) + nt * 8 + (lane & 3) * 2;
                    float2 o = *reinterpret_cast<float2*>(crow + n);
                    float ex = __expf(acc[mt][nt][half * 2]     + o.x);
                    float ey = __expf(acc[mt][nt][half * 2 + 1] + o.y);
                    float2 v; v.x = ex; v.y = ey;
                    *reinterpret_cast<float2*>(crow + n) = v;
                    rowsum += ex + ey;
                }
                rowsum += __shfl_xor_sync(0xffffffffu, rowsum, 1);
                rowsum += __shfl_xor_sync(0xffffffffu, rowsum, 2);
                if ((lane & 3) == 0)
                    atomicAdd(&Zp[(long long)m * 1024 + z], rowsum);
            } else if (EPI == 2) {
                float invZ = 1.0f / Zp[(long long)m * 1024 + z];
#pragma unroll
                for (int nt = 0; nt < NTL; nt++) {
                    int n = tile_n + wn * (BN / 2) + nt * 8 + (lane & 3) * 2;
                    float2 o = *reinterpret_cast<float2*>(crow + n);
                    float2 v;
                    v.x = (acc[mt][nt][half * 2]     + o.x) * invZ;
                    v.y = (acc[mt][nt][half * 2 + 1] + o.y) * invZ;
                    *reinterpret_cast<float2*>(crow + n) = v;
                }
            } else {
#pragma unroll
                for (int nt = 0; nt < NTL; nt++) {
                    int n = tile_n + wn * (BN / 2) + nt * 8 + (lane & 3) * 2;
                    float vx = acc[mt][nt][half * 2];
                    float vy = acc[mt][nt][half * 2 + 1];
                    if (bias) { vx += bias[n]; vy += bias[n + 1]; }
                    vx *= alpha; vy *= alpha;
                    if (beta != 0.0f) {
                        float2 o = *reinterpret_cast<float2*>(crow + n);
                        vx += beta * o.x; vy += beta * o.y;
                    }
                    float2 v; v.x = vx; v.y = vy;
                    *reinterpret_cast<float2*>(crow + n) = v;
                }
            }
        }
    }
}

// =================== small kernels ===========================================
__global__ __launch_bounds__(256)
void zeroZ_kernel(float* __restrict__ Z)
{
    Z[blockIdx.x * 256 + threadIdx.x] = 0.0f;
}

// avg weights for one l-group: E layout (b, l_local, s), stride b = 131072
__global__ __launch_bounds__(256)
void avgw_kernel(const float* __restrict__ Ebuf, const float* __restrict__ Zg,
                 float* __restrict__ outb, int g)
{
    int ll = blockIdx.x;    // 0..127 local l
    int n  = blockIdx.y;    // 0..7
    __shared__ float invZ[8];
    if (threadIdx.x < 8)
        invZ[threadIdx.x] = 0.125f / Zg[(n * 8 + threadIdx.x) * 1024 + ll];
    __syncthreads();
    int s = threadIdx.x * 4;
    float4 acc = make_float4(0.f, 0.f, 0.f, 0.f);
#pragma unroll
    for (int h = 0; h < 8; h++) {
        const float4 v = *reinterpret_cast<const float4*>(
            Ebuf + (long long)(n * 8 + h) * (LGRP * 1024) + (long long)ll * 1024 + s);
        float w = invZ[h];
        acc.x += v.x * w; acc.y += v.y * w; acc.z += v.z * w; acc.w += v.w * w;
    }
    *reinterpret_cast<float4*>(
        outb + (((long long)n) << 20) + (long long)(g * LGRP + ll) * 1024 + s) = acc;
}

// =================== launch ==================================================
extern "C" void kernel_launch(void* const* d_in, const int* in_sizes, int n_in,
                              void* d_out, int out_size)
{
    const float* query = (const float*)d_in[0];
    const float* key   = (const float*)d_in[1];
    const float* value = (const float*)d_in[2];
    const float* pos_k = (const float*)d_in[3];
    const float* pos_v = (const float*)d_in[4];
    const float* Wq = (const float*)d_in[5];
    const float* bq = (const float*)d_in[6];
    const float* Wk = (const float*)d_in[7];
    const float* bk = (const float*)d_in[8];
    const float* Wv = (const float*)d_in[9];
    const float* bv = (const float*)d_in[10];
    const float* Wo = (const float*)d_in[11];
    const float* bo = (const float*)d_in[12];
    float* out = (float*)d_out;

    float *qp, *kp, *vp, *Ebuf, *Zbuf, *Obuf;
    cudaGetSymbolAddress((void**)&qp,   g_qp);
    cudaGetSymbolAddress((void**)&kp,   g_kp);
    cudaGetSymbolAddress((void**)&vp,   g_vp);
    cudaGetSymbolAddress((void**)&Ebuf, g_E);
    cudaGetSymbolAddress((void**)&Zbuf, g_Z);
    cudaGetSymbolAddress((void**)&Obuf, g_O);

    // dynamic smem sizes (double-buffered)
    const int SM_128_128 = 2 * (128 + 128) * 144;   // 73728
    const int SM_64_128  = 2 * (64 + 128) * 144;    // 55296
    const int SM_64_64   = 2 * (64 + 64) * 144;     // 36864

    cudaFuncSetAttribute(mma_gemm<128, 128, true, 0>,
        cudaFuncAttributeMaxDynamicSharedMemorySize, SM_128_128);
    cudaFuncSetAttribute(mma_gemm<64, 128, true, 1>,
        cudaFuncAttributeMaxDynamicSharedMemorySize, SM_64_128);
    cudaFuncSetAttribute(mma_gemm<64, 64, false, 0>,
        cudaFuncAttributeMaxDynamicSharedMemorySize, SM_64_64);
    cudaFuncSetAttribute(mma_gemm<64, 64, false, 2>,
        cudaFuncAttributeMaxDynamicSharedMemorySize, SM_64_64);

    // 0. Zero softmax denominators (filled by EXPZ epilogue atomics)
    zeroZ_kernel<<<256, 256>>>(Zbuf);

    // 1-3. Projections: (8192 x 512) @ W^T + b;  B(n,k) = W[n*512+k]
    mma_gemm<128, 128, true, 0><<<dim3(4, 64, 1), 256, SM_128_128>>>(
        query, 0, 512,  Wq, 0, 512,  qp, 0, 512,  bq, 0.125f, 0.0f, 512, nullptr);
    mma_gemm<128, 128, true, 0><<<dim3(4, 64, 1), 256, SM_128_128>>>(
        key,   0, 512,  Wk, 0, 512,  kp, 0, 512,  bk, 1.0f,   0.0f, 512, nullptr);
    mma_gemm<128, 128, true, 0><<<dim3(4, 64, 1), 256, SM_128_128>>>(
        value, 0, 512,  Wv, 0, 512,  vp, 0, 512,  bv, 1.0f,   0.0f, 512, nullptr);

    // 4. Per l-group pipeline; E scratch (33.5MB) reused each group -> L2-resident
    for (int g = 0; g < NGRP; g++) {
        const float* qpg   = qp + (long long)g * LGRP * 4096;
        const float* poskg = pos_k + (long long)g * LGRP * 65536;
        const float* posvg = pos_v + (long long)g * LGRP * 65536;
        float* Og          = Obuf + (long long)g * LGRP * 4096;
        float* Zg          = Zbuf + g * LGRP;

        // 4a. Content scores: E[b, ll, s] = sum_d q[b, g*128+ll, d] k[b, s, d]
        mma_gemm<128, 128, true, 0><<<dim3(8, 1, 64), 256, SM_128_128>>>(
            qpg, 64, 4096,  kp, 64, 4096,
            Ebuf, (long long)LGRP * 1024, 1024,
            nullptr, 1.0f, 0.0f, 64, nullptr);

        // 4b. Pos-key + exp + rowsum (batch ll): E = exp(content + q@pos_k^T); Z += rowsum
        mma_gemm<64, 128, true, 1><<<dim3(8, 1, LGRP), 256, SM_64_128>>>(
            qpg, 4096, 64,  poskg, 65536, 64,
            Ebuf, 1024, (long long)LGRP * 1024,
            nullptr, 1.0f, 1.0f, 64, Zg);

        // 4c. Content output (batch b): O[ll, b*64+d] = sum_s E[b,ll,s] v[s, b*64+d]
        mma_gemm<64, 64, false, 0><<<dim3(1, 2, 64), 256, SM_64_64>>>(
            Ebuf, (long long)LGRP * 1024, 1024,  vp, 64, 4096,
            Og, 64, 4096, nullptr, 1.0f, 0.0f, 1024, nullptr);

        // 4d. Pos-value + normalize (batch ll): O = (O_old + E@pos_v[l]) / Z
        mma_gemm<64, 64, false, 2><<<dim3(1, 1, LGRP), 256, SM_64_64>>>(
            Ebuf, 1024, (long long)LGRP * 1024,  posvg, 65536, 64,
            Og, 4096, 64, nullptr, 1.0f, 1.0f, 1024, Zg);

        // 4e. Averaged weights for this group
        avgw_kernel<<<dim3(LGRP, 8), 256>>>(Ebuf, Zg, out + 4194304, g);
    }

    // 5. Output projection
    mma_gemm<128, 128, true, 0><<<dim3(4, 64, 1), 256, SM_128_128>>>(
        Obuf, 0, 512,  Wo, 0, 512,  out, 0, 512,  bo, 1.0f, 0.0f, 512, nullptr);
}

// round 6
// speedup vs baseline: 1.3245x; 1.3245x over previous
#include <cuda_runtime.h>
#include <cuda_bf16.h>
#include <cuda_fp16.h>
#include <cstdint>

// Problem constants
#define LQ 1024
#define SQ 1024
#define NBATCH 8
#define EDIM 512
#define BHEADS 64   // NBATCH * HHEADS

// ---------------- scratch (device globals; no allocations allowed) ----------
__device__ float  g_qp[LQ * NBATCH * EDIM];         // (l, b, d)
__device__ float  g_kp[SQ * NBATCH * EDIM];
__device__ float  g_vp[SQ * NBATCH * EDIM];
__device__ float  g_S[67108864];                    // (b, l, s) content scores fp32
__device__ __half g_E[67108864];                    // (b, l, s) exp scores fp16
__device__ float  g_Z[BHEADS * LQ];                 // (b, l) row sums
__device__ float  g_O[LQ * NBATCH * EDIM];          // (l, b, d) numerator out

// =================== helpers ================================================
__device__ __forceinline__ uint32_t smem_u32(const void* p) {
    uint32_t a;
    asm("{ .reg .u64 t; cvta.to.shared.u64 t, %1; cvt.u32.u64 %0, t; }" : "=r"(a) : "l"(p));
    return a;
}

__device__ __forceinline__ void ldsm_x4(uint32_t* r, uint32_t addr) {
    asm volatile("ldmatrix.sync.aligned.m8n8.x4.shared.b16 {%0,%1,%2,%3}, [%4];"
        : "=r"(r[0]), "=r"(r[1]), "=r"(r[2]), "=r"(r[3]) : "r"(addr));
}

__device__ __forceinline__ void mma_bf16(float* c, const uint32_t* a, const uint32_t* b) {
    asm volatile(
        "mma.sync.aligned.m16n8k16.row.col.f32.bf16.bf16.f32 "
        "{%0,%1,%2,%3}, {%4,%5,%6,%7}, {%8,%9}, {%0,%1,%2,%3};"
        : "+f"(c[0]), "+f"(c[1]), "+f"(c[2]), "+f"(c[3])
        : "r"(a[0]), "r"(a[1]), "r"(a[2]), "r"(a[3]), "r"(b[0]), "r"(b[1]));
}
__device__ __forceinline__ void mma_f16(float* c, const uint32_t* a, const uint32_t* b) {
    asm volatile(
        "mma.sync.aligned.m16n8k16.row.col.f32.f16.f16.f32 "
        "{%0,%1,%2,%3}, {%4,%5,%6,%7}, {%8,%9}, {%0,%1,%2,%3};"
        : "+f"(c[0]), "+f"(c[1]), "+f"(c[2]), "+f"(c[3])
        : "r"(a[0]), "r"(a[1]), "r"(a[2]), "r"(a[3]), "r"(b[0]), "r"(b[1]));
}

// fp32 -> (hi, lo) bf16 split (3-term path)
__device__ __forceinline__ void split2b(float x, float y, uint32_t& hi, uint32_t& lo) {
    __nv_bfloat16 h0 = __float2bfloat16(x);
    __nv_bfloat16 h1 = __float2bfloat16(y);
    __nv_bfloat16 l0 = __float2bfloat16(x - __bfloat162float(h0));
    __nv_bfloat16 l1 = __float2bfloat16(y - __bfloat162float(h1));
    hi = (uint32_t)__bfloat16_as_ushort(h0) | ((uint32_t)__bfloat16_as_ushort(h1) << 16);
    lo = (uint32_t)__bfloat16_as_ushort(l0) | ((uint32_t)__bfloat16_as_ushort(l1) << 16);
}
// fp32 -> (hi, lo) fp16 split (2-term path)
__device__ __forceinline__ void split2h(float x, float y, uint32_t& hi, uint32_t& lo) {
    __half h0 = __float2half_rn(x);
    __half h1 = __float2half_rn(y);
    __half l0 = __float2half_rn(x - __half2float(h0));
    __half l1 = __float2half_rn(y - __half2float(h1));
    hi = (uint32_t)__half_as_ushort(h0) | ((uint32_t)__half_as_ushort(h1) << 16);
    lo = (uint32_t)__half_as_ushort(l0) | ((uint32_t)__half_as_ushort(l1) << 16);
}

// =================== HMMA strided batched GEMM (512 threads, pipelined) =====
// C[z][m][n] = epilogue( sum_k A(m,k)*B(n,k) )
// A(m,k) = A[z*aBS + m*aRS + k]                 (k contiguous; fp32 or fp16 per AF16)
// B(n,k) = BKFAST ? B[z*bBS + n*bS + k]         (k contiguous)
//                 : B[z*bBS + k*bS + n]         (n contiguous)  (fp32 source)
// C at    C[z*cBS + m*cRS + n]                  (n contiguous)
// EPI: 0 = fp32 C = alpha*(acc+bias) + beta*Cold
//      1 = EXPZ: e = exp(acc + Cin[m,n]); store fp16 e into C; atomicAdd rowsum Zp[m*1024+z]
//      2 = DIVZ: fp32 C = (acc + Cold) / Zp[m*1024+z]
// AF16: A is fp16 (direct, 1 frag), B split fp16, f16 MMA 2 terms.
// else: A,B split bf16, 3 terms.
// 512 threads = 16 warps (4m x 4n). BK = 32.
template<int BM, int BN, bool BKFAST, int EPI, bool AF16>
__global__ __launch_bounds__(512)
void mma_gemm(const void* __restrict__ Ap, long long aBS, long long aRS,
              const float* __restrict__ B, long long bBS, long long bS,
              void* __restrict__ Cp, long long cBS, long long cRS,
              const float* __restrict__ Cin,
              const float* __restrict__ bias, float alpha, float beta,
              int K, float* __restrict__ Zp)
{
    constexpr int MT   = BM / 64;          // m16 tiles per warp
    constexpr int NTL  = BN / 32;          // n8 tiles per warp
    constexpr int NPAIR = NTL / 2;
    constexpr int ROWB = 144;
    constexpr int STG  = (BM + BN) * ROWB;
    constexpr int AREG  = BM * 16 / 512;   // float2 (or half2-u32) per thread
    constexpr int BREG2 = BKFAST ? BN * 16 / 512 : 1;
    constexpr int BREG1 = BKFAST ? 1 : BN * 32 / 512;

    extern __shared__ __align__(16) char smem[];

    const int tid  = threadIdx.x;
    const int wid  = tid >> 5;
    const int lane = tid & 31;
    const int wm   = wid >> 2;             // 0..3
    const int wn   = wid & 3;              // 0..3
    const int mat  = lane >> 3;
    const int rw   = lane & 7;

    const int tile_n = blockIdx.x * BN;
    const int tile_m = blockIdx.y * BM;
    const int z      = blockIdx.z;

    const float*  A32 = (const float*)Ap;
    const __half* A16 = (const __half*)Ap;
    const float*  Az32 = A32 + (long long)z * aBS + (long long)tile_m * aRS;
    const __half* Az16 = A16 + (long long)z * aBS + (long long)tile_m * aRS;
    const float*  Bz   = B + (long long)z * bBS;

    float acc[MT][NTL][4];
#pragma unroll
    for (int i = 0; i < MT; i++)
#pragma unroll
        for (int j = 0; j < NTL; j++)
#pragma unroll
            for (int q = 0; q < 4; q++) acc[i][j][q] = 0.0f;

    const uint32_t s_u = smem_u32(smem);
    const uint32_t aAddr0 = s_u + (uint32_t)(wm * (BM / 4) + rw + (mat & 1) * 8) * ROWB
                                + (uint32_t)((mat >> 1) * 16);
    const uint32_t bAddr0 = s_u + (uint32_t)(BM * ROWB)
                                + (uint32_t)(wn * (BN / 4) + rw + (mat >> 1) * 8) * ROWB
                                + (uint32_t)((mat & 1) * 16);

    float2   aReg[AF16 ? 1 : AREG];
    uint32_t aRegH[AF16 ? AREG : 1];
    float2   bReg2[BREG2];
    float    bReg1[BREG1];

    auto ldgA = [&](int ch) {
        if (AF16) {
            const __half* p = Az16 + (ch << 5);
#pragma unroll
            for (int j = 0; j < AREG; j++) {
                int i = tid + j * 512;
                int k2 = i & 15, r = i >> 4;
                aRegH[j] = *reinterpret_cast<const uint32_t*>(p + (long long)r * aRS + k2 * 2);
            }
        } else {
            const float* p = Az32 + (ch << 5);
#pragma unroll
            for (int j = 0; j < AREG; j++) {
                int i = tid + j * 512;
                int k2 = i & 15, r = i >> 4;
                aReg[j] = *reinterpret_cast<const float2*>(p + (long long)r * aRS + k2 * 2);
            }
        }
    };
    auto stsA = [&](int st) {
        char* base = smem + st * STG;
#pragma unroll
        for (int j = 0; j < AREG; j++) {
            int i = tid + j * 512;
            int k2 = i & 15, r = i >> 4;
            char* rp = base + r * ROWB + k2 * 4;
            if (AF16) {
                *reinterpret_cast<uint32_t*>(rp) = aRegH[j];
            } else {
                uint32_t hi, lo;
                split2b(aReg[j].x, aReg[j].y, hi, lo);
                *reinterpret_cast<uint32_t*>(rp)      = hi;
                *reinterpret_cast<uint32_t*>(rp + 64) = lo;
            }
        }
    };
    auto ldgB = [&](int ch) {
        if (BKFAST) {
            const float* p = Bz + (long long)tile_n * bS + (ch << 5);
#pragma unroll
            for (int j = 0; j < BREG2; j++) {
                int i = tid + j * 512;
                int k2 = i & 15, r = i >> 4;
                bReg2[j] = *reinterpret_cast<const float2*>(p + (long long)r * bS + k2 * 2);
            }
        } else {
            const float* p = Bz + tile_n + (long long)(ch << 5) * bS;
#pragma unroll
            for (int j = 0; j < BREG1; j++) {
                int i = tid + j * 512;
                int n = i & (BN - 1), k = i / BN;
                bReg1[j] = p[(long long)k * bS + n];
            }
        }
    };
    auto stsB = [&](int st) {
        char* base = smem + st * STG + BM * ROWB;
        if (BKFAST) {
#pragma unroll
            for (int j = 0; j < BREG2; j++) {
                int i = tid + j * 512;
                int k2 = i & 15, r = i >> 4;
                uint32_t hi, lo;
                if (AF16) split2h(bReg2[j].x, bReg2[j].y, hi, lo);
                else      split2b(bReg2[j].x, bReg2[j].y, hi, lo);
                char* rp = base + r * ROWB + k2 * 4;
                *reinterpret_cast<uint32_t*>(rp)      = hi;
                *reinterpret_cast<uint32_t*>(rp + 64) = lo;
            }
        } else {
#pragma unroll
            for (int j = 0; j < BREG1; j++) {
                int i = tid + j * 512;
                int n = i & (BN - 1), k = i / BN;
                float v = bReg1[j];
                unsigned short h, l;
                if (AF16) {
                    __half hh = __float2half_rn(v);
                    __half ll = __float2half_rn(v - __half2float(hh));
                    h = __half_as_ushort(hh); l = __half_as_ushort(ll);
                } else {
                    __nv_bfloat16 hh = __float2bfloat16(v);
                    __nv_bfloat16 ll = __float2bfloat16(v - __bfloat162float(hh));
                    h = __bfloat16_as_ushort(hh); l = __bfloat16_as_ushort(ll);
                }
                char* rp = base + n * ROWB + k * 2;
                *reinterpret_cast<unsigned short*>(rp)      = h;
                *reinterpret_cast<unsigned short*>(rp + 64) = l;
            }
        }
    };
    auto compute = [&](int st) {
        const uint32_t off = (uint32_t)(st * STG);
#pragma unroll
        for (int ks = 0; ks < 2; ks++) {
            uint32_t aH[MT][4], aL[MT][4];
#pragma unroll
            for (int mt = 0; mt < MT; mt++) {
                uint32_t ad = aAddr0 + off + (uint32_t)(mt * 16 * ROWB) + (uint32_t)(ks * 32);
                ldsm_x4(aH[mt], ad);
                if (!AF16) ldsm_x4(aL[mt], ad + 64);
            }
            uint32_t bH[NTL][2], bL[NTL][2];
#pragma unroll
            for (int p = 0; p < NPAIR; p++) {
                uint32_t bd = bAddr0 + off + (uint32_t)(p * 16 * ROWB) + (uint32_t)(ks * 32);
                uint32_t t[4];
                ldsm_x4(t, bd);
                bH[2 * p][0] = t[0]; bH[2 * p][1] = t[1];
                bH[2 * p + 1][0] = t[2]; bH[2 * p + 1][1] = t[3];
                ldsm_x4(t, bd + 64);
                bL[2 * p][0] = t[0]; bL[2 * p][1] = t[1];
                bL[2 * p + 1][0] = t[2]; bL[2 * p + 1][1] = t[3];
            }
#pragma unroll
            for (int mt = 0; mt < MT; mt++)
#pragma unroll
                for (int nt = 0; nt < NTL; nt++) {
                    if (AF16) {
                        mma_f16(acc[mt][nt], aH[mt], bH[nt]);
                        mma_f16(acc[mt][nt], aH[mt], bL[nt]);
                    } else {
                        mma_bf16(acc[mt][nt], aH[mt], bH[nt]);
                        mma_bf16(acc[mt][nt], aH[mt], bL[nt]);
                        mma_bf16(acc[mt][nt], aL[mt], bH[nt]);
                    }
                }
        }
    };

    const int nch = K >> 5;
    ldgA(0); ldgB(0);
    stsA(0); stsB(0);
    __syncthreads();
    for (int ch = 0; ch < nch; ch++) {
        const bool more = (ch + 1 < nch);
        if (more) { ldgA(ch + 1); ldgB(ch + 1); }
        compute(ch & 1);
        if (more) {
            stsA((ch + 1) & 1); stsB((ch + 1) & 1);
            __syncthreads();
        }
    }

    // ---- epilogue ----
#pragma unroll
    for (int mt = 0; mt < MT; mt++) {
        int m0 = tile_m + wm * (BM / 4) + mt * 16 + (lane >> 2);
#pragma unroll
        for (int half = 0; half < 2; half++) {
            int m = m0 + half * 8;
            if (EPI == 1) {
                const float* cinrow = Cin + (long long)z * cBS + (long long)m * cRS;
                __half* erow = (__half*)Cp + (long long)z * cBS + (long long)m * cRS;
                float rowsum = 0.0f;
#pragma unroll
                for (int nt = 0; nt < NTL; nt++) {
                    int n = tile_n + wn * (BN / 4) + nt * 8 + (lane & 3) * 2;
                    float2 o = *reinterpret_cast<const float2*>(cinrow + n);
                    float ex = __expf(acc[mt][nt][half * 2]     + o.x);
                    float ey = __expf(acc[mt][nt][half * 2 + 1] + o.y);
                    __half2 hv = __floats2half2_rn(ex, ey);
                    *reinterpret_cast<__half2*>(erow + n) = hv;
                    rowsum += ex + ey;
                }
                rowsum += __shfl_xor_sync(0xffffffffu, rowsum, 1);
                rowsum += __shfl_xor_sync(0xffffffffu, rowsum, 2);
                if ((lane & 3) == 0)
                    atomicAdd(&Zp[(long long)m * 1024 + z], rowsum);
            } else if (EPI == 2) {
                float* crow = (float*)Cp + (long long)z * cBS + (long long)m * cRS;
                float invZ = 1.0f / Zp[(long long)m * 1024 + z];
#pragma unroll
                for (int nt = 0; nt < NTL; nt++) {
                    int n = tile_n + wn * (BN / 4) + nt * 8 + (lane & 3) * 2;
                    float2 o = *reinterpret_cast<float2*>(crow + n);
                    float2 v;
                    v.x = (acc[mt][nt][half * 2]     + o.x) * invZ;
                    v.y = (acc[mt][nt][half * 2 + 1] + o.y) * invZ;
                    *reinterpret_cast<float2*>(crow + n) = v;
                }
            } else {
                float* crow = (float*)Cp + (long long)z * cBS + (long long)m * cRS;
#pragma unroll
                for (int nt = 0; nt < NTL; nt++) {
                    int n = tile_n + wn * (BN / 4) + nt * 8 + (lane & 3) * 2;
                    float vx = acc[mt][nt][half * 2];
                    float vy = acc[mt][nt][half * 2 + 1];
                    if (bias) { vx += bias[n]; vy += bias[n + 1]; }
                    vx *= alpha; vy *= alpha;
                    if (beta != 0.0f) {
                        float2 o = *reinterpret_cast<float2*>(crow + n);
                        vx += beta * o.x; vy += beta * o.y;
                    }
                    float2 v; v.x = vx; v.y = vy;
                    *reinterpret_cast<float2*>(crow + n) = v;
                }
            }
        }
    }
}

// =================== small kernels ===========================================
__global__ __launch_bounds__(256)
void zeroZ_kernel(float* __restrict__ Z)
{
    Z[blockIdx.x * 256 + threadIdx.x] = 0.0f;
}

__global__ __launch_bounds__(256)
void avgw_kernel(const __half* __restrict__ Ebuf, const float* __restrict__ Z,
                 float* __restrict__ out)
{
    int l = blockIdx.x;
    int n = blockIdx.y;
    __shared__ float invZ[8];
    if (threadIdx.x < 8)
        invZ[threadIdx.x] = 0.125f / Z[(n * 8 + threadIdx.x) * 1024 + l];
    __syncthreads();
    int s = threadIdx.x * 4;
    float4 acc = make_float4(0.f, 0.f, 0.f, 0.f);
#pragma unroll
    for (int h = 0; h < 8; h++) {
        const __half* p = Ebuf + (((long long)(n * 8 + h)) << 20) + (long long)l * 1024 + s;
        float2 a = __half22float2(*reinterpret_cast<const __half2*>(p));
        float2 b = __half22float2(*reinterpret_cast<const __half2*>(p + 2));
        float w = invZ[h];
        acc.x += a.x * w; acc.y += a.y * w; acc.z += b.x * w; acc.w += b.y * w;
    }
    *reinterpret_cast<float4*>(
        out + (((long long)n) << 20) + (long long)l * 1024 + s) = acc;
}

// =================== launch ==================================================
extern "C" void kernel_launch(void* const* d_in, const int* in_sizes, int n_in,
                              void* d_out, int out_size)
{
    const float* query = (const float*)d_in[0];
    const float* key   = (const float*)d_in[1];
    const float* value = (const float*)d_in[2];
    const float* pos_k = (const float*)d_in[3];
    const float* pos_v = (const float*)d_in[4];
    const float* Wq = (const float*)d_in[5];
    const float* bq = (const float*)d_in[6];
    const float* Wk = (const float*)d_in[7];
    const float* bk = (const float*)d_in[8];
    const float* Wv = (const float*)d_in[9];
    const float* bv = (const float*)d_in[10];
    const float* Wo = (const float*)d_in[11];
    const float* bo = (const float*)d_in[12];
    float* out = (float*)d_out;

    float *qp, *kp, *vp, *Sbuf, *Zbuf, *Obuf;
    __half* Ebuf;
    cudaGetSymbolAddress((void**)&qp,   g_qp);
    cudaGetSymbolAddress((void**)&kp,   g_kp);
    cudaGetSymbolAddress((void**)&vp,   g_vp);
    cudaGetSymbolAddress((void**)&Sbuf, g_S);
    cudaGetSymbolAddress((void**)&Ebuf, g_E);
    cudaGetSymbolAddress((void**)&Zbuf, g_Z);
    cudaGetSymbolAddress((void**)&Obuf, g_O);

    // dynamic smem sizes (double-buffered)
    const int SM_128_128 = 2 * (128 + 128) * 144;   // 73728
    const int SM_64_128  = 2 * (64 + 128) * 144;    // 55296
    const int SM_128_64  = 2 * (128 + 64) * 144;    // 55296
    const int SM_64_64   = 2 * (64 + 64) * 144;     // 36864

    cudaFuncSetAttribute(mma_gemm<128, 128, true, 0, false>,
        cudaFuncAttributeMaxDynamicSharedMemorySize, SM_128_128);
    cudaFuncSetAttribute(mma_gemm<64, 128, true, 1, false>,
        cudaFuncAttributeMaxDynamicSharedMemorySize, SM_64_128);
    cudaFuncSetAttribute(mma_gemm<128, 64, false, 0, true>,
        cudaFuncAttributeMaxDynamicSharedMemorySize, SM_128_64);
    cudaFuncSetAttribute(mma_gemm<64, 64, false, 2, true>,
        cudaFuncAttributeMaxDynamicSharedMemorySize, SM_64_64);

    // 0. Zero softmax denominators
    zeroZ_kernel<<<256, 256>>>(Zbuf);

    // 1-3. Projections: (8192 x 512) @ W^T + b
    mma_gemm<128, 128, true, 0, false><<<dim3(4, 64, 1), 512, SM_128_128>>>(
        query, 0, 512,  Wq, 0, 512,  qp, 0, 512,  nullptr, bq, 0.125f, 0.0f, 512, nullptr);
    mma_gemm<128, 128, true, 0, false><<<dim3(4, 64, 1), 512, SM_128_128>>>(
        key,   0, 512,  Wk, 0, 512,  kp, 0, 512,  nullptr, bk, 1.0f,   0.0f, 512, nullptr);
    mma_gemm<128, 128, true, 0, false><<<dim3(4, 64, 1), 512, SM_128_128>>>(
        value, 0, 512,  Wv, 0, 512,  vp, 0, 512,  nullptr, bv, 1.0f,   0.0f, 512, nullptr);

    // 4. Content scores (batch b=64): S[b,l,s] = sum_d q[b,l,d] k[b,s,d]  (fp32)
    mma_gemm<128, 128, true, 0, false><<<dim3(8, 8, 64), 512, SM_128_128>>>(
        qp, 64, 4096,  kp, 64, 4096,  Sbuf, (long long)1 << 20, 1024,
        nullptr, nullptr, 1.0f, 0.0f, 64, nullptr);

    // 5. Pos-key + exp + rowsum (batch l=1024):
    //    E[b,l,s] = fp16( exp(S + q@pos_k[l]^T) ); Z[b,l] += rowsums
    mma_gemm<64, 128, true, 1, false><<<dim3(8, 1, 1024), 512, SM_64_128>>>(
        qp, 4096, 64,  pos_k, 65536, 64,  Ebuf, 1024, (long long)1 << 20,
        Sbuf, nullptr, 1.0f, 1.0f, 64, Zbuf);

    // 6. Content output (batch b=64, fp16 A): O[l, b*64+d] = sum_s E[b,l,s] v[s, b*64+d]
    mma_gemm<128, 64, false, 0, true><<<dim3(1, 8, 64), 512, SM_128_64>>>(
        Ebuf, (long long)1 << 20, 1024,  vp, 64, 4096,  Obuf, 64, 4096,
        nullptr, nullptr, 1.0f, 0.0f, 1024, nullptr);

    // 7. Pos-value + normalize (batch l=1024, fp16 A):
    //    O[l, b*64+d] = (O_old + sum_s E[b,l,s] pos_v[l,s,d]) / Z[b,l]
    mma_gemm<64, 64, false, 2, true><<<dim3(1, 1, 1024), 512, SM_64_64>>>(
        Ebuf, 1024, (long long)1 << 20,  pos_v, 65536, 64,  Obuf, 4096, 64,
        nullptr, nullptr, 1.0f, 1.0f, 1024, Zbuf);

    // 8. Output projection
    mma_gemm<128, 128, true, 0, false><<<dim3(4, 64, 1), 512, SM_128_128>>>(
        Obuf, 0, 512,  Wo, 0, 512,  out, 0, 512,  nullptr, bo, 1.0f, 0.0f, 512, nullptr);

    // 9. Averaged weights
    avgw_kernel<<<dim3(1024, 8, 1), 256>>>(Ebuf, Zbuf, out + 4194304);
}

// round 7
// speedup vs baseline: 1.5577x; 1.1761x over previous
#include <cuda_runtime.h>
#include <cuda_bf16.h>
#include <cuda_fp16.h>
#include <cstdint>

// Problem constants
#define LQ 1024
#define SQ 1024
#define NBATCH 8
#define EDIM 512
#define BHEADS 64   // NBATCH * HHEADS

// ---------------- scratch (device globals; no allocations allowed) ----------
__device__ float  g_qp[LQ * NBATCH * EDIM];         // (l, b, d)
__device__ float  g_kp[SQ * NBATCH * EDIM];
__device__ float  g_vp[SQ * NBATCH * EDIM];
__device__ float  g_S[67108864];                    // (b, l, s) content scores fp32
__device__ __half g_E[67108864];                    // (b, l, s) exp scores fp16
__device__ float  g_Z[BHEADS * LQ];                 // (b, l) row sums
__device__ float  g_O[LQ * NBATCH * EDIM];          // (l, b, d) numerator out

// =================== helpers ================================================
__device__ __forceinline__ uint32_t smem_u32(const void* p) {
    uint32_t a;
    asm("{ .reg .u64 t; cvta.to.shared.u64 t, %1; cvt.u32.u64 %0, t; }" : "=r"(a) : "l"(p));
    return a;
}

__device__ __forceinline__ void ldsm_x4(uint32_t* r, uint32_t addr) {
    asm volatile("ldmatrix.sync.aligned.m8n8.x4.shared.b16 {%0,%1,%2,%3}, [%4];"
        : "=r"(r[0]), "=r"(r[1]), "=r"(r[2]), "=r"(r[3]) : "r"(addr));
}

__device__ __forceinline__ void mma_bf16(float* c, const uint32_t* a, const uint32_t* b) {
    asm volatile(
        "mma.sync.aligned.m16n8k16.row.col.f32.bf16.bf16.f32 "
        "{%0,%1,%2,%3}, {%4,%5,%6,%7}, {%8,%9}, {%0,%1,%2,%3};"
        : "+f"(c[0]), "+f"(c[1]), "+f"(c[2]), "+f"(c[3])
        : "r"(a[0]), "r"(a[1]), "r"(a[2]), "r"(a[3]), "r"(b[0]), "r"(b[1]));
}
__device__ __forceinline__ void mma_f16(float* c, const uint32_t* a, const uint32_t* b) {
    asm volatile(
        "mma.sync.aligned.m16n8k16.row.col.f32.f16.f16.f32 "
        "{%0,%1,%2,%3}, {%4,%5,%6,%7}, {%8,%9}, {%0,%1,%2,%3};"
        : "+f"(c[0]), "+f"(c[1]), "+f"(c[2]), "+f"(c[3])
        : "r"(a[0]), "r"(a[1]), "r"(a[2]), "r"(a[3]), "r"(b[0]), "r"(b[1]));
}

// fp32 -> (hi, lo) bf16 split (3-term path)
__device__ __forceinline__ void split2b(float x, float y, uint32_t& hi, uint32_t& lo) {
    __nv_bfloat16 h0 = __float2bfloat16(x);
    __nv_bfloat16 h1 = __float2bfloat16(y);
    __nv_bfloat16 l0 = __float2bfloat16(x - __bfloat162float(h0));
    __nv_bfloat16 l1 = __float2bfloat16(y - __bfloat162float(h1));
    hi = (uint32_t)__bfloat16_as_ushort(h0) | ((uint32_t)__bfloat16_as_ushort(h1) << 16);
    lo = (uint32_t)__bfloat16_as_ushort(l0) | ((uint32_t)__bfloat16_as_ushort(l1) << 16);
}
// fp32 -> (hi, lo) fp16 split (2-term path with exact fp16 A)
__device__ __forceinline__ void split2h(float x, float y, uint32_t& hi, uint32_t& lo) {
    __half h0 = __float2half_rn(x);
    __half h1 = __float2half_rn(y);
    __half l0 = __float2half_rn(x - __half2float(h0));
    __half l1 = __float2half_rn(y - __half2float(h1));
    hi = (uint32_t)__half_as_ushort(h0) | ((uint32_t)__half_as_ushort(h1) << 16);
    lo = (uint32_t)__half_as_ushort(l0) | ((uint32_t)__half_as_ushort(l1) << 16);
}

// =================== HMMA strided batched GEMM (256 threads, pipelined) =====
// C[z][m][n] = epilogue( sum_k A(m,k)*B(n,k) )
// A(m,k) = A[z*aBS + m*aRS + k]                 (k contiguous; fp32, or fp16 if AF16)
// B(n,k) = BKFAST ? B[z*bBS + n*bS + k]         (k contiguous)
//                 : B[z*bBS + k*bS + n]         (n contiguous)  (fp32 source)
// C at    C[z*cBS + m*cRS + n]                  (n contiguous)
// EPI: 0 = fp32 C = alpha*(acc+bias) + beta*Cold
//      1 = EXPZ: e = exp(acc + Cin[..]); store fp16 e into C; atomicAdd rowsum Zp[m*1024+z]
//      2 = DIVZ: fp32 C = (acc + Cold) / Zp[m*1024+z]
// AF16: A is fp16 (exact, 1 fragment), B split fp16, 2-term f16 MMA.
// else: A,B split bf16, 3-term bf16 MMA.
// 256 threads = 8 warps (4 m x 2 n). BK = 32. Double-buffered smem + reg prefetch.
template<int BM, int BN, bool BKFAST, int EPI, bool AF16>
__global__ __launch_bounds__(256)
void mma_gemm(const void* __restrict__ Ap, long long aBS, long long aRS,
              const float* __restrict__ B, long long bBS, long long bS,
              void* __restrict__ Cp, long long cBS, long long cRS,
              const float* __restrict__ Cin,
              const float* __restrict__ bias, float alpha, float beta,
              int K, float* __restrict__ Zp)
{
    constexpr int MT   = BM / 64;          // m16 tiles per warp
    constexpr int NTL  = BN / 16;          // n8 tiles per warp
    constexpr int NPAIR = NTL / 2;
    constexpr int ROWB = 144;
    constexpr int STG  = (BM + BN) * ROWB;
    constexpr int AREG  = BM * 16 / 256;   // 4B-units per thread (float2 / u32-half2)
    constexpr int BREG2 = BKFAST ? BN * 16 / 256 : 1;
    constexpr int BREG1 = BKFAST ? 1 : BN * 32 / 256;

    extern __shared__ __align__(16) char smem[];

    const int tid  = threadIdx.x;
    const int wid  = tid >> 5;
    const int lane = tid & 31;
    const int wm   = wid >> 1;             // 0..3
    const int wn   = wid & 1;              // 0..1
    const int mat  = lane >> 3;
    const int rw   = lane & 7;

    const int tile_n = blockIdx.x * BN;
    const int tile_m = blockIdx.y * BM;
    const int z      = blockIdx.z;

    const float*  Az32 = (const float*)Ap  + (long long)z * aBS + (long long)tile_m * aRS;
    const __half* Az16 = (const __half*)Ap + (long long)z * aBS + (long long)tile_m * aRS;
    const float*  Bz   = B + (long long)z * bBS;

    float acc[MT][NTL][4];
#pragma unroll
    for (int i = 0; i < MT; i++)
#pragma unroll
        for (int j = 0; j < NTL; j++)
#pragma unroll
            for (int q = 0; q < 4; q++) acc[i][j][q] = 0.0f;

    const uint32_t s_u = smem_u32(smem);
    const uint32_t aAddr0 = s_u + (uint32_t)(wm * (BM / 4) + rw + (mat & 1) * 8) * ROWB
                                + (uint32_t)((mat >> 1) * 16);
    const uint32_t bAddr0 = s_u + (uint32_t)(BM * ROWB)
                                + (uint32_t)(wn * (BN / 2) + rw + (mat >> 1) * 8) * ROWB
                                + (uint32_t)((mat & 1) * 16);

    float2   aReg[AF16 ? 1 : AREG];
    uint32_t aRegH[AF16 ? AREG : 1];
    float2   bReg2[BREG2];
    float    bReg1[BREG1];

    auto ldgA = [&](int ch) {
        if (AF16) {
            const __half* p = Az16 + (ch << 5);
#pragma unroll
            for (int j = 0; j < AREG; j++) {
                int i = tid + j * 256;
                int k2 = i & 15, r = i >> 4;
                aRegH[j] = *reinterpret_cast<const uint32_t*>(p + (long long)r * aRS + k2 * 2);
            }
        } else {
            const float* p = Az32 + (ch << 5);
#pragma unroll
            for (int j = 0; j < AREG; j++) {
                int i = tid + j * 256;
                int k2 = i & 15, r = i >> 4;
                aReg[j] = *reinterpret_cast<const float2*>(p + (long long)r * aRS + k2 * 2);
            }
        }
    };
    auto stsA = [&](int st) {
        char* base = smem + st * STG;
#pragma unroll
        for (int j = 0; j < AREG; j++) {
            int i = tid + j * 256;
            int k2 = i & 15, r = i >> 4;
            char* rp = base + r * ROWB + k2 * 4;
            if (AF16) {
                *reinterpret_cast<uint32_t*>(rp) = aRegH[j];
            } else {
                uint32_t hi, lo;
                split2b(aReg[j].x, aReg[j].y, hi, lo);
                *reinterpret_cast<uint32_t*>(rp)      = hi;
                *reinterpret_cast<uint32_t*>(rp + 64) = lo;
            }
        }
    };
    auto ldgB = [&](int ch) {
        if (BKFAST) {
            const float* p = Bz + (long long)tile_n * bS + (ch << 5);
#pragma unroll
            for (int j = 0; j < BREG2; j++) {
                int i = tid + j * 256;
                int k2 = i & 15, r = i >> 4;
                bReg2[j] = *reinterpret_cast<const float2*>(p + (long long)r * bS + k2 * 2);
            }
        } else {
            const float* p = Bz + tile_n + (long long)(ch << 5) * bS;
#pragma unroll
            for (int j = 0; j < BREG1; j++) {
                int i = tid + j * 256;
                int n = i & (BN - 1), k = i / BN;
                bReg1[j] = p[(long long)k * bS + n];
            }
        }
    };
    auto stsB = [&](int st) {
        char* base = smem + st * STG + BM * ROWB;
        if (BKFAST) {
#pragma unroll
            for (int j = 0; j < BREG2; j++) {
                int i = tid + j * 256;
                int k2 = i & 15, r = i >> 4;
                uint32_t hi, lo;
                if (AF16) split2h(bReg2[j].x, bReg2[j].y, hi, lo);
                else      split2b(bReg2[j].x, bReg2[j].y, hi, lo);
                char* rp = base + r * ROWB + k2 * 4;
                *reinterpret_cast<uint32_t*>(rp)      = hi;
                *reinterpret_cast<uint32_t*>(rp + 64) = lo;
            }
        } else {
#pragma unroll
            for (int j = 0; j < BREG1; j++) {
                int i = tid + j * 256;
                int n = i & (BN - 1), k = i / BN;
                float v = bReg1[j];
                unsigned short h, l;
                if (AF16) {
                    __half hh = __float2half_rn(v);
                    __half ll = __float2half_rn(v - __half2float(hh));
                    h = __half_as_ushort(hh); l = __half_as_ushort(ll);
                } else {
                    __nv_bfloat16 hh = __float2bfloat16(v);
                    __nv_bfloat16 ll = __float2bfloat16(v - __bfloat162float(hh));
                    h = __bfloat16_as_ushort(hh); l = __bfloat16_as_ushort(ll);
                }
                char* rp = base + n * ROWB + k * 2;
                *reinterpret_cast<unsigned short*>(rp)      = h;
                *reinterpret_cast<unsigned short*>(rp + 64) = l;
            }
        }
    };
    auto compute = [&](int st) {
        const uint32_t off = (uint32_t)(st * STG);
#pragma unroll
        for (int ks = 0; ks < 2; ks++) {
            uint32_t aH[MT][4], aL[MT][4];
#pragma unroll
            for (int mt = 0; mt < MT; mt++) {
                uint32_t ad = aAddr0 + off + (uint32_t)(mt * 16 * ROWB) + (uint32_t)(ks * 32);
                ldsm_x4(aH[mt], ad);
                if (!AF16) ldsm_x4(aL[mt], ad + 64);
            }
            uint32_t bH[NTL][2], bL[NTL][2];
#pragma unroll
            for (int p = 0; p < NPAIR; p++) {
                uint32_t bd = bAddr0 + off + (uint32_t)(p * 16 * ROWB) + (uint32_t)(ks * 32);
                uint32_t t[4];
                ldsm_x4(t, bd);
                bH[2 * p][0] = t[0]; bH[2 * p][1] = t[1];
                bH[2 * p + 1][0] = t[2]; bH[2 * p + 1][1] = t[3];
                ldsm_x4(t, bd + 64);
                bL[2 * p][0] = t[0]; bL[2 * p][1] = t[1];
                bL[2 * p + 1][0] = t[2]; bL[2 * p + 1][1] = t[3];
            }
#pragma unroll
            for (int mt = 0; mt < MT; mt++)
#pragma unroll
                for (int nt = 0; nt < NTL; nt++) {
                    if (AF16) {
                        mma_f16(acc[mt][nt], aH[mt], bH[nt]);
                        mma_f16(acc[mt][nt], aH[mt], bL[nt]);
                    } else {
                        mma_bf16(acc[mt][nt], aH[mt], bH[nt]);
                        mma_bf16(acc[mt][nt], aH[mt], bL[nt]);
                        mma_bf16(acc[mt][nt], aL[mt], bH[nt]);
                    }
                }
        }
    };

    const int nch = K >> 5;
    ldgA(0); ldgB(0);
    stsA(0); stsB(0);
    __syncthreads();
    for (int ch = 0; ch < nch; ch++) {
        const bool more = (ch + 1 < nch);
        if (more) { ldgA(ch + 1); ldgB(ch + 1); }
        compute(ch & 1);
        if (more) {
            stsA((ch + 1) & 1); stsB((ch + 1) & 1);
            __syncthreads();
        }
    }

    // ---- epilogue ----
#pragma unroll
    for (int mt = 0; mt < MT; mt++) {
        int m0 = tile_m + wm * (BM / 4) + mt * 16 + (lane >> 2);
#pragma unroll
        for (int half = 0; half < 2; half++) {
            int m = m0 + half * 8;
            if (EPI == 1) {
                const float* cinrow = Cin + (long long)z * cBS + (long long)m * cRS;
                __half* erow = (__half*)Cp + (long long)z * cBS + (long long)m * cRS;
                float rowsum = 0.0f;
#pragma unroll
                for (int nt = 0; nt < NTL; nt++) {
                    int n = tile_n + wn * (BN / 2) + nt * 8 + (lane & 3) * 2;
                    float2 o = *reinterpret_cast<const float2*>(cinrow + n);
                    float ex = __expf(acc[mt][nt][half * 2]     + o.x);
                    float ey = __expf(acc[mt][nt][half * 2 + 1] + o.y);
                    *reinterpret_cast<__half2*>(erow + n) = __floats2half2_rn(ex, ey);
                    rowsum += ex + ey;
                }
                rowsum += __shfl_xor_sync(0xffffffffu, rowsum, 1);
                rowsum += __shfl_xor_sync(0xffffffffu, rowsum, 2);
                if ((lane & 3) == 0)
                    atomicAdd(&Zp[(long long)m * 1024 + z], rowsum);
            } else if (EPI == 2) {
                float* crow = (float*)Cp + (long long)z * cBS + (long long)m * cRS;
                float invZ = 1.0f / Zp[(long long)m * 1024 + z];
#pragma unroll
                for (int nt = 0; nt < NTL; nt++) {
                    int n = tile_n + wn * (BN / 2) + nt * 8 + (lane & 3) * 2;
                    float2 o = *reinterpret_cast<float2*>(crow + n);
                    float2 v;
                    v.x = (acc[mt][nt][half * 2]     + o.x) * invZ;
                    v.y = (acc[mt][nt][half * 2 + 1] + o.y) * invZ;
                    *reinterpret_cast<float2*>(crow + n) = v;
                }
            } else {
                float* crow = (float*)Cp + (long long)z * cBS + (long long)m * cRS;
#pragma unroll
                for (int nt = 0; nt < NTL; nt++) {
                    int n = tile_n + wn * (BN / 2) + nt * 8 + (lane & 3) * 2;
                    float vx = acc[mt][nt][half * 2];
                    float vy = acc[mt][nt][half * 2 + 1];
                    if (bias) { vx += bias[n]; vy += bias[n + 1]; }
                    vx *= alpha; vy *= alpha;
                    if (beta != 0.0f) {
                        float2 o = *reinterpret_cast<float2*>(crow + n);
                        vx += beta * o.x; vy += beta * o.y;
                    }
                    float2 v; v.x = vx; v.y = vy;
                    *reinterpret_cast<float2*>(crow + n) = v;
                }
            }
        }
    }
}

// =================== small kernels ===========================================
__global__ __launch_bounds__(256)
void zeroZ_kernel(float* __restrict__ Z)
{
    Z[blockIdx.x * 256 + threadIdx.x] = 0.0f;
}

__global__ __launch_bounds__(256)
void avgw_kernel(const __half* __restrict__ Ebuf, const float* __restrict__ Z,
                 float* __restrict__ out)
{
    int l = blockIdx.x;
    int n = blockIdx.y;
    __shared__ float invZ[8];
    if (threadIdx.x < 8)
        invZ[threadIdx.x] = 0.125f / Z[(n * 8 + threadIdx.x) * 1024 + l];
    __syncthreads();
    int s = threadIdx.x * 4;
    float4 acc = make_float4(0.f, 0.f, 0.f, 0.f);
#pragma unroll
    for (int h = 0; h < 8; h++) {
        const __half2* p = reinterpret_cast<const __half2*>(
            Ebuf + (((long long)(n * 8 + h)) << 20) + (long long)l * 1024 + s);
        float2 a = __half22float2(p[0]);
        float2 b = __half22float2(p[1]);
        float w = invZ[h];
        acc.x += a.x * w; acc.y += a.y * w; acc.z += b.x * w; acc.w += b.y * w;
    }
    *reinterpret_cast<float4*>(
        out + (((long long)n) << 20) + (long long)l * 1024 + s) = acc;
}

// =================== launch ==================================================
extern "C" void kernel_launch(void* const* d_in, const int* in_sizes, int n_in,
                              void* d_out, int out_size)
{
    const float* query = (const float*)d_in[0];
    const float* key   = (const float*)d_in[1];
    const float* value = (const float*)d_in[2];
    const float* pos_k = (const float*)d_in[3];
    const float* pos_v = (const float*)d_in[4];
    const float* Wq = (const float*)d_in[5];
    const float* bq = (const float*)d_in[6];
    const float* Wk = (const float*)d_in[7];
    const float* bk = (const float*)d_in[8];
    const float* Wv = (const float*)d_in[9];
    const float* bv = (const float*)d_in[10];
    const float* Wo = (const float*)d_in[11];
    const float* bo = (const float*)d_in[12];
    float* out = (float*)d_out;

    float *qp, *kp, *vp, *Sbuf, *Zbuf, *Obuf;
    __half* Ebuf;
    cudaGetSymbolAddress((void**)&qp,   g_qp);
    cudaGetSymbolAddress((void**)&kp,   g_kp);
    cudaGetSymbolAddress((void**)&vp,   g_vp);
    cudaGetSymbolAddress((void**)&Sbuf, g_S);
    cudaGetSymbolAddress((void**)&Ebuf, g_E);
    cudaGetSymbolAddress((void**)&Zbuf, g_Z);
    cudaGetSymbolAddress((void**)&Obuf, g_O);

    // dynamic smem sizes (double-buffered)
    const int SM_128_128 = 2 * (128 + 128) * 144;   // 73728
    const int SM_64_128  = 2 * (64 + 128) * 144;    // 55296
    const int SM_128_64  = 2 * (128 + 64) * 144;    // 55296
    const int SM_64_64   = 2 * (64 + 64) * 144;     // 36864

    cudaFuncSetAttribute(mma_gemm<128, 128, true, 0, false>,
        cudaFuncAttributeMaxDynamicSharedMemorySize, SM_128_128);
    cudaFuncSetAttribute(mma_gemm<64, 128, true, 1, false>,
        cudaFuncAttributeMaxDynamicSharedMemorySize, SM_64_128);
    cudaFuncSetAttribute(mma_gemm<128, 64, false, 0, true>,
        cudaFuncAttributeMaxDynamicSharedMemorySize, SM_128_64);
    cudaFuncSetAttribute(mma_gemm<64, 64, false, 2, true>,
        cudaFuncAttributeMaxDynamicSharedMemorySize, SM_64_64);

    // 0. Zero softmax denominators
    zeroZ_kernel<<<256, 256>>>(Zbuf);

    // 1-3. Projections: (8192 x 512) @ W^T + b
    mma_gemm<128, 128, true, 0, false><<<dim3(4, 64, 1), 256, SM_128_128>>>(
        query, 0, 512,  Wq, 0, 512,  qp, 0, 512,  nullptr, bq, 0.125f, 0.0f, 512, nullptr);
    mma_gemm<128, 128, true, 0, false><<<dim3(4, 64, 1), 256, SM_128_128>>>(
        key,   0, 512,  Wk, 0, 512,  kp, 0, 512,  nullptr, bk, 1.0f,   0.0f, 512, nullptr);
    mma_gemm<128, 128, true, 0, false><<<dim3(4, 64, 1), 256, SM_128_128>>>(
        value, 0, 512,  Wv, 0, 512,  vp, 0, 512,  nullptr, bv, 1.0f,   0.0f, 512, nullptr);

    // 4. Content scores (batch b=64): S[b,l,s] = sum_d q[b,l,d] k[b,s,d]  (fp32)
    mma_gemm<128, 128, true, 0, false><<<dim3(8, 8, 64), 256, SM_128_128>>>(
        qp, 64, 4096,  kp, 64, 4096,  Sbuf, (long long)1 << 20, 1024,
        nullptr, nullptr, 1.0f, 0.0f, 64, nullptr);

    // 5. Pos-key + exp + rowsum (batch l=1024):
    //    E[b,l,s] = fp16( exp(S + q@pos_k[l]^T) ); Z[b,l] += rowsums
    mma_gemm<64, 128, true, 1, false><<<dim3(8, 1, 1024), 256, SM_64_128>>>(
        qp, 4096, 64,  pos_k, 65536, 64,  Ebuf, 1024, (long long)1 << 20,
        Sbuf, nullptr, 1.0f, 1.0f, 64, Zbuf);

    // 6. Content output (batch b=64, fp16 A, 2-term):
    //    O[l, b*64+d] = sum_s E[b,l,s] v[s, b*64+d]
    mma_gemm<128, 64, false, 0, true><<<dim3(1, 8, 64), 256, SM_128_64>>>(
        Ebuf, (long long)1 << 20, 1024,  vp, 64, 4096,  Obuf, 64, 4096,
        nullptr, nullptr, 1.0f, 0.0f, 1024, nullptr);

    // 7. Pos-value + normalize (batch l=1024, fp16 A, 2-term):
    //    O[l, b*64+d] = (O_old + sum_s E[b,l,s] pos_v[l,s,d]) / Z[b,l]
    mma_gemm<64, 64, false, 2, true><<<dim3(1, 1, 1024), 256, SM_64_64>>>(
        Ebuf, 1024, (long long)1 << 20,  pos_v, 65536, 64,  Obuf, 4096, 64,
        nullptr, nullptr, 1.0f, 1.0f, 1024, Zbuf);

    // 8. Output projection
    mma_gemm<128, 128, true, 0, false><<<dim3(4, 64, 1), 256, SM_128_128>>>(
        Obuf, 0, 512,  Wo, 0, 512,  out, 0, 512,  nullptr, bo, 1.0f, 0.0f, 512, nullptr);

    // 9. Averaged weights
    avgw_kernel<<<dim3(1024, 8, 1), 256>>>(Ebuf, Zbuf, out + 4194304);
}